// round 9
// baseline (speedup 1.0000x reference)
#include <cuda_runtime.h>
#include <cuda_fp16.h>
#include <cstdint>

#define NN 2048
#define DD 512
#define KPC 8
#define TM 128
#define TN 64
#define KS 64
#define NSLAB (DD / KS)
#define NTILES 272          // 32 diagonal-band + 240 strictly-above

// ---------------- scratch (no allocations allowed) ----------------
__device__ __half g_xf[NN * DD];             // fp16 normalized (MMA operand)
__device__ float g_sq[NN];
__device__ float g_pos[NN * 8];              // P_k = exp(pos dist), self slot = 0
__device__ float g_thr[NN * 8];              // thr_k = p_k + eps (validity on d)
__device__ float g_row[NN * 4];              // cnt, trip_sum, pos_sum, neg_sum
__device__ int g_done;

// ---------------- helpers ----------------
__device__ __forceinline__ uint32_t smem_to_u32(const void* p) {
    uint32_t a;
    asm("{ .reg .u64 t; cvta.to.shared.u64 t, %1; cvt.u32.u64 %0, t; }" : "=r"(a) : "l"(p));
    return a;
}
__device__ __forceinline__ float fast_exp2(float x) { float y; asm("ex2.approx.f32 %0, %1;" : "=f"(y) : "f"(x)); return y; }
__device__ __forceinline__ float fast_log2(float x) { float y; asm("lg2.approx.f32 %0, %1;" : "=f"(y) : "f"(x)); return y; }
__device__ __forceinline__ float warp_sum(float v) {
    #pragma unroll
    for (int o = 16; o; o >>= 1) v += __shfl_xor_sync(0xffffffffu, v, o);
    return v;
}

#define CPA(dst, src) \
    asm volatile("cp.async.cg.shared.global [%0], [%1], 16;" :: "r"(dst), "l"(src))
#define CPA_COMMIT() asm volatile("cp.async.commit_group;" ::: "memory")

__device__ __forceinline__ void ldm_x4(uint32_t* r, uint32_t addr) {
    asm volatile("ldmatrix.sync.aligned.m8n8.x4.shared.b16 {%0,%1,%2,%3}, [%4];"
                 : "=r"(r[0]), "=r"(r[1]), "=r"(r[2]), "=r"(r[3]) : "r"(addr));
}
__device__ __forceinline__ void mma_fp16(float* c, const uint32_t* a, uint32_t b0, uint32_t b1) {
    asm volatile(
        "mma.sync.aligned.m16n8k16.row.col.f32.f16.f16.f32 "
        "{%0,%1,%2,%3}, {%4,%5,%6,%7}, {%8,%9}, {%0,%1,%2,%3};"
        : "+f"(c[0]), "+f"(c[1]), "+f"(c[2]), "+f"(c[3])
        : "r"(a[0]), "r"(a[1]), "r"(a[2]), "r"(a[3]), "r"(b0), "r"(b1));
}

// ---------------------------------------------------------------------------
// 1) prep: normalize + fp16 + sq + per-class positives (P, thr) + init g_row
// ---------------------------------------------------------------------------
#define XPAD 4
__global__ __launch_bounds__(256) void prep_kernel(const float* __restrict__ in) {
    __shared__ float xs[KPC][DD + XPAD];
    __shared__ float ssq[KPC];
    const int cls = blockIdx.x;
    const int tid = threadIdx.x;
    const int w = tid >> 5;
    const int l = tid & 31;
    const int row = cls * KPC + w;
    if (cls == 0 && tid == 0) g_done = 0;

    float4 v[4];
    const float4* src = reinterpret_cast<const float4*>(in + row * DD) + l * 4;
    #pragma unroll
    for (int q = 0; q < 4; q++) v[q] = src[q];
    float ss = 0.0f;
    #pragma unroll
    for (int q = 0; q < 4; q++)
        ss += v[q].x * v[q].x + v[q].y * v[q].y + v[q].z * v[q].z + v[q].w * v[q].w;
    ss = warp_sum(ss);
    float s = 4.0f * rsqrtf(ss);

    __half2* pf = reinterpret_cast<__half2*>(g_xf + row * DD + l * 16);
    #pragma unroll
    for (int q = 0; q < 4; q++) {
        float4 o4 = make_float4(v[q].x * s, v[q].y * s, v[q].z * s, v[q].w * s);
        xs[w][l * 16 + q * 4 + 0] = o4.x;
        xs[w][l * 16 + q * 4 + 1] = o4.y;
        xs[w][l * 16 + q * 4 + 2] = o4.z;
        xs[w][l * 16 + q * 4 + 3] = o4.w;
        pf[q * 2 + 0] = __half2(__float2half_rn(o4.x), __float2half_rn(o4.y));
        pf[q * 2 + 1] = __half2(__float2half_rn(o4.z), __float2half_rn(o4.w));
    }
    if (l == 0) { g_sq[row] = ss * s * s; ssq[w] = ss * s * s; }
    __syncthreads();

    if (tid < 64) {
        const float L2E = 1.4426950408889634f;
        int a = tid >> 3, b = tid & 7;
        float dot = 0.0f;
        #pragma unroll 4
        for (int q = 0; q < DD; q += 4) {
            dot += xs[a][q + 0] * xs[b][q + 0] + xs[a][q + 1] * xs[b][q + 1]
                 + xs[a][q + 2] * xs[b][q + 2] + xs[a][q + 3] * xs[b][q + 3];
        }
        int ia = cls * KPC + a;
        float p = ssq[a] + ssq[b] - 2.0f * dot;
        bool self = (a == b);
        g_pos[ia * 8 + b] = self ? 0.0f : fast_exp2(p * L2E);
        g_thr[ia * 8 + b] = self ? -1.0e30f : (p + 2.9447e-4f);
        float ps = self ? 0.0f : p;
        ps += __shfl_xor_sync(0xffffffffu, ps, 1);
        ps += __shfl_xor_sync(0xffffffffu, ps, 2);
        ps += __shfl_xor_sync(0xffffffffu, ps, 4);
        if (b == 0) {
            g_row[ia * 4 + 0] = 0.0f;
            g_row[ia * 4 + 1] = 0.0f;
            g_row[ia * 4 + 2] = ps;
            g_row[ia * 4 + 3] = 0.0f;
        }
    }
}

// ---------------------------------------------------------------------------
// 2) fused symmetric HMMA Gram + dual-orientation epilogue + finalize
// ---------------------------------------------------------------------------
#define SM_SQI  0
#define SM_SQJ  512
#define SM_PI   1024
#define SM_THRI 5120
#define SM_PJ   9216
#define SM_THRJ 11264
#define SM_BUF  13312
#define A_OFF 0
#define B_OFF 16384
#define STAGESZ 24576
#define SMEM_TOTAL (SM_BUF + 3 * STAGESZ)   // 87040 B

__device__ __forceinline__ void load_slab_async(uint32_t smb, int buf, int s,
                                                int bi, int bj, int tid) {
    const int k0 = s * KS;
    const uint32_t bufb = smb + SM_BUF + buf * STAGESZ;
    // A: 128 rows x 8 chunks of 16B; 2 threads per row
    {
        const int row = tid >> 1;
        const int cb = (tid & 1) * 4;
        const char* sp = reinterpret_cast<const char*>(g_xf + (bi + row) * DD + k0);
        uint32_t dA = bufb + A_OFF + row * 128;
        #pragma unroll
        for (int c = 0; c < 4; c++) {
            int ch = cb + c;
            CPA(dA + (((ch ^ (row & 7))) << 4), sp + ch * 16);
        }
    }
    // B: 64 rows x 8 chunks; 4 threads per row
    {
        const int row = tid >> 2;
        const int cb = (tid & 3) * 2;
        const char* sp = reinterpret_cast<const char*>(g_xf + (bj + row) * DD + k0);
        uint32_t dB = bufb + B_OFF + row * 128;
        #pragma unroll
        for (int c = 0; c < 2; c++) {
            int ch = cb + c;
            CPA(dB + (((ch ^ (row & 7))) << 4), sp + ch * 16);
        }
    }
}

__global__ __launch_bounds__(256, 2) void fused_kernel(float* __restrict__ out, int out_size) {
    extern __shared__ char smem[];
    const int tid = threadIdx.x;
    const int wid = tid >> 5;
    const int lane = tid & 31;

    // tile decode: b<32 -> diagonal band (ti, tj=2ti+(b&1)); else strictly above
    int ti, tj;
    bool diag;
    {
        int b = blockIdx.x;
        if (b < 32) { ti = b >> 1; tj = 2 * ti + (b & 1); diag = true; }
        else {
            int r = b - 32; ti = 0; int c = 30;
            while (r >= c) { r -= c; ti++; c -= 2; }
            tj = 2 * ti + 2 + r; diag = false;
        }
    }
    const int bi = ti * TM;
    const int bj = tj * TN;
    const int mloc = (wid >> 1) * 32;
    const int nloc = (wid & 1) * 32;
    const uint32_t smb = smem_to_u32(smem);
    float* sSqi  = reinterpret_cast<float*>(smem + SM_SQI);
    float* sSqj  = reinterpret_cast<float*>(smem + SM_SQJ);
    float* sPi   = reinterpret_cast<float*>(smem + SM_PI);
    float* sThrI = reinterpret_cast<float*>(smem + SM_THRI);
    float* sPj   = reinterpret_cast<float*>(smem + SM_PJ);
    float* sThrJ = reinterpret_cast<float*>(smem + SM_THRJ);

    load_slab_async(smb, 0, 0, bi, bj, tid);
    CPA_COMMIT();
    load_slab_async(smb, 1, 1, bi, bj, tid);
    CPA_COMMIT();

    if (tid < 128) sSqi[tid] = g_sq[bi + tid];
    else if (tid < 192) sSqj[tid - 128] = g_sq[bj + (tid - 128)];
    reinterpret_cast<float4*>(sPi)[tid]   = reinterpret_cast<const float4*>(g_pos + bi * 8)[tid];
    reinterpret_cast<float4*>(sThrI)[tid] = reinterpret_cast<const float4*>(g_thr + bi * 8)[tid];
    if (tid < 128) {
        reinterpret_cast<float4*>(sPj)[tid]   = reinterpret_cast<const float4*>(g_pos + bj * 8)[tid];
        reinterpret_cast<float4*>(sThrJ)[tid] = reinterpret_cast<const float4*>(g_thr + bj * 8)[tid];
    }

    float acc[2][4][4];
    #pragma unroll
    for (int mi = 0; mi < 2; mi++)
        #pragma unroll
        for (int ni = 0; ni < 4; ni++)
            #pragma unroll
            for (int r = 0; r < 4; r++) acc[mi][ni][r] = 0.0f;

    const int rA = (lane & 7) + (((lane >> 3) & 1) << 3);
    const int cSel = lane >> 4;
    const int x7 = lane & 7;

    // 3-stage pipeline, one barrier per slab
    #pragma unroll 1
    for (int s = 0; s < NSLAB; s++) {
        asm volatile("cp.async.wait_group 1;" ::: "memory");
        __syncthreads();
        if (s + 2 < NSLAB) load_slab_async(smb, (s + 2) % 3, s + 2, bi, bj, tid);
        CPA_COMMIT();

        const uint32_t base = smb + SM_BUF + (s % 3) * STAGESZ;
        #pragma unroll
        for (int ks = 0; ks < 4; ks++) {
            uint32_t af[2][4];
            #pragma unroll
            for (int mi = 0; mi < 2; mi++) {
                int row = mloc + mi * 16 + rA;
                uint32_t ad = base + A_OFF + row * 128 + ((((2 * ks + cSel) ^ x7)) << 4);
                ldm_x4(af[mi], ad);
            }
            uint32_t bfr[2][4];
            #pragma unroll
            for (int nt = 0; nt < 2; nt++) {
                int row = nloc + nt * 16 + rA;
                uint32_t bd = base + B_OFF + row * 128 + ((((2 * ks + cSel) ^ x7)) << 4);
                ldm_x4(bfr[nt], bd);
            }
            #pragma unroll
            for (int mi = 0; mi < 2; mi++)
                #pragma unroll
                for (int nt = 0; nt < 2; nt++) {
                    mma_fp16(acc[mi][2 * nt],     af[mi], bfr[nt][0], bfr[nt][2]);
                    mma_fp16(acc[mi][2 * nt + 1], af[mi], bfr[nt][1], bfr[nt][3]);
                }
        }
    }

    // ---- triplet epilogue ----
    const float L2E = 1.4426950408889634f;
    const float LN2 = 0.6931471805599453f;

    if (diag) {
        // row-orientation only, with class-block skip (cols within same 128-row block)
        #pragma unroll
        for (int mi = 0; mi < 2; mi++) {
            #pragma unroll
            for (int h = 0; h < 2; h++) {
                const int rl = mloc + mi * 16 + h * 8 + (lane >> 2);
                const int gi = bi + rl;
                const float sqi = sSqi[rl];
                const float4 p0 = *reinterpret_cast<const float4*>(sPi + rl * 8);
                const float4 p1 = *reinterpret_cast<const float4*>(sPi + rl * 8 + 4);
                const float4 t0 = *reinterpret_cast<const float4*>(sThrI + rl * 8);
                const float4 t1 = *reinterpret_cast<const float4*>(sThrI + rl * 8 + 4);
                const int skipni = ((gi >> 3) - (bj >> 3)) - (nloc >> 3);
                float cnt = 0.0f, trip = 0.0f, neg = 0.0f;
                #pragma unroll
                for (int ni = 0; ni < 4; ni++) {
                    if (ni == skipni) continue;
                    #pragma unroll
                    for (int rr = 0; rr < 2; rr++) {
                        const int cl = nloc + ni * 8 + (lane & 3) * 2 + rr;
                        const float d = sqi + sSqj[cl] - 2.0f * acc[mi][ni][h * 2 + rr];
                        neg += d;
                        const float en = fast_exp2(-d * L2E);
                        bool v0 = d < t0.x, v1 = d < t0.y, v2 = d < t0.z, v3 = d < t0.w;
                        bool v4 = d < t1.x, v5 = d < t1.y, v6 = d < t1.z, v7 = d < t1.w;
                        cnt += (v0 ? 1.0f : 0.0f) + (v1 ? 1.0f : 0.0f) + (v2 ? 1.0f : 0.0f) + (v3 ? 1.0f : 0.0f)
                             + (v4 ? 1.0f : 0.0f) + (v5 ? 1.0f : 0.0f) + (v6 ? 1.0f : 0.0f) + (v7 ? 1.0f : 0.0f);
                        float pa = v0 ? fmaf(p0.x, en, 1.0f) : 1.0f;
                        pa *= v1 ? fmaf(p0.y, en, 1.0f) : 1.0f;
                        pa *= v2 ? fmaf(p0.z, en, 1.0f) : 1.0f;
                        pa *= v3 ? fmaf(p0.w, en, 1.0f) : 1.0f;
                        float pb = v4 ? fmaf(p1.x, en, 1.0f) : 1.0f;
                        pb *= v5 ? fmaf(p1.y, en, 1.0f) : 1.0f;
                        pb *= v6 ? fmaf(p1.z, en, 1.0f) : 1.0f;
                        pb *= v7 ? fmaf(p1.w, en, 1.0f) : 1.0f;
                        trip += LN2 * (fast_log2(pa) + fast_log2(pb));
                    }
                }
                cnt  += __shfl_xor_sync(0xffffffffu, cnt, 1);
                cnt  += __shfl_xor_sync(0xffffffffu, cnt, 2);
                trip += __shfl_xor_sync(0xffffffffu, trip, 1);
                trip += __shfl_xor_sync(0xffffffffu, trip, 2);
                neg  += __shfl_xor_sync(0xffffffffu, neg, 1);
                neg  += __shfl_xor_sync(0xffffffffu, neg, 2);
                if ((lane & 3) == 0) {
                    atomicAdd(&g_row[gi * 4 + 0], cnt);
                    atomicAdd(&g_row[gi * 4 + 1], trip);
                    atomicAdd(&g_row[gi * 4 + 3], neg);
                }
            }
        }
    } else {
        // strictly-above tile: all elements are cross-class; dual orientation
        float ccnt[8], ctrip[8], cneg[8];
        #pragma unroll
        for (int q = 0; q < 8; q++) { ccnt[q] = 0.0f; ctrip[q] = 0.0f; cneg[q] = 0.0f; }

        #pragma unroll
        for (int mi = 0; mi < 2; mi++) {
            #pragma unroll
            for (int h = 0; h < 2; h++) {
                const int rl = mloc + mi * 16 + h * 8 + (lane >> 2);
                const int gi = bi + rl;
                const float sqi = sSqi[rl];
                const float4 p0 = *reinterpret_cast<const float4*>(sPi + rl * 8);
                const float4 p1 = *reinterpret_cast<const float4*>(sPi + rl * 8 + 4);
                const float4 t0 = *reinterpret_cast<const float4*>(sThrI + rl * 8);
                const float4 t1 = *reinterpret_cast<const float4*>(sThrI + rl * 8 + 4);
                float cnt = 0.0f, trip = 0.0f, neg = 0.0f;
                #pragma unroll
                for (int ni = 0; ni < 4; ni++) {
                    #pragma unroll
                    for (int rr = 0; rr < 2; rr++) {
                        const int q = ni * 2 + rr;
                        const int cl = nloc + ni * 8 + (lane & 3) * 2 + rr;
                        const float d = sqi + sSqj[cl] - 2.0f * acc[mi][ni][h * 2 + rr];
                        const float en = fast_exp2(-d * L2E);
                        // row orientation (anchor gi)
                        neg += d;
                        {
                            bool v0 = d < t0.x, v1 = d < t0.y, v2 = d < t0.z, v3 = d < t0.w;
                            bool v4 = d < t1.x, v5 = d < t1.y, v6 = d < t1.z, v7 = d < t1.w;
                            cnt += (v0 ? 1.0f : 0.0f) + (v1 ? 1.0f : 0.0f) + (v2 ? 1.0f : 0.0f) + (v3 ? 1.0f : 0.0f)
                                 + (v4 ? 1.0f : 0.0f) + (v5 ? 1.0f : 0.0f) + (v6 ? 1.0f : 0.0f) + (v7 ? 1.0f : 0.0f);
                            float pa = v0 ? fmaf(p0.x, en, 1.0f) : 1.0f;
                            pa *= v1 ? fmaf(p0.y, en, 1.0f) : 1.0f;
                            pa *= v2 ? fmaf(p0.z, en, 1.0f) : 1.0f;
                            pa *= v3 ? fmaf(p0.w, en, 1.0f) : 1.0f;
                            float pb = v4 ? fmaf(p1.x, en, 1.0f) : 1.0f;
                            pb *= v5 ? fmaf(p1.y, en, 1.0f) : 1.0f;
                            pb *= v6 ? fmaf(p1.z, en, 1.0f) : 1.0f;
                            pb *= v7 ? fmaf(p1.w, en, 1.0f) : 1.0f;
                            trip += LN2 * (fast_log2(pa) + fast_log2(pb));
                        }
                        // col orientation (anchor gj = bj + cl)
                        {
                            const float4 q0 = *reinterpret_cast<const float4*>(sPj + cl * 8);
                            const float4 q1 = *reinterpret_cast<const float4*>(sPj + cl * 8 + 4);
                            const float4 u0 = *reinterpret_cast<const float4*>(sThrJ + cl * 8);
                            const float4 u1 = *reinterpret_cast<const float4*>(sThrJ + cl * 8 + 4);
                            bool w0 = d < u0.x, w1 = d < u0.y, w2 = d < u0.z, w3 = d < u0.w;
                            bool w4 = d < u1.x, w5 = d < u1.y, w6 = d < u1.z, w7 = d < u1.w;
                            cneg[q] += d;
                            ccnt[q] += (w0 ? 1.0f : 0.0f) + (w1 ? 1.0f : 0.0f) + (w2 ? 1.0f : 0.0f) + (w3 ? 1.0f : 0.0f)
                                     + (w4 ? 1.0f : 0.0f) + (w5 ? 1.0f : 0.0f) + (w6 ? 1.0f : 0.0f) + (w7 ? 1.0f : 0.0f);
                            float qa = w0 ? fmaf(q0.x, en, 1.0f) : 1.0f;
                            qa *= w1 ? fmaf(q0.y, en, 1.0f) : 1.0f;
                            qa *= w2 ? fmaf(q0.z, en, 1.0f) : 1.0f;
                            qa *= w3 ? fmaf(q0.w, en, 1.0f) : 1.0f;
                            float qb = w4 ? fmaf(q1.x, en, 1.0f) : 1.0f;
                            qb *= w5 ? fmaf(q1.y, en, 1.0f) : 1.0f;
                            qb *= w6 ? fmaf(q1.z, en, 1.0f) : 1.0f;
                            qb *= w7 ? fmaf(q1.w, en, 1.0f) : 1.0f;
                            ctrip[q] += LN2 * (fast_log2(qa) + fast_log2(qb));
                        }
                    }
                }
                cnt  += __shfl_xor_sync(0xffffffffu, cnt, 1);
                cnt  += __shfl_xor_sync(0xffffffffu, cnt, 2);
                trip += __shfl_xor_sync(0xffffffffu, trip, 1);
                trip += __shfl_xor_sync(0xffffffffu, trip, 2);
                neg  += __shfl_xor_sync(0xffffffffu, neg, 1);
                neg  += __shfl_xor_sync(0xffffffffu, neg, 2);
                if ((lane & 3) == 0) {
                    atomicAdd(&g_row[gi * 4 + 0], cnt);
                    atomicAdd(&g_row[gi * 4 + 1], trip);
                    atomicAdd(&g_row[gi * 4 + 3], neg);
                }
            }
        }
        // column reductions: sum over row-lanes (xor 4, 8, 16)
        #pragma unroll
        for (int q = 0; q < 8; q++) {
            float c = ccnt[q], t = ctrip[q], n = cneg[q];
            c += __shfl_xor_sync(0xffffffffu, c, 4);
            c += __shfl_xor_sync(0xffffffffu, c, 8);
            c += __shfl_xor_sync(0xffffffffu, c, 16);
            t += __shfl_xor_sync(0xffffffffu, t, 4);
            t += __shfl_xor_sync(0xffffffffu, t, 8);
            t += __shfl_xor_sync(0xffffffffu, t, 16);
            n += __shfl_xor_sync(0xffffffffu, n, 4);
            n += __shfl_xor_sync(0xffffffffu, n, 8);
            n += __shfl_xor_sync(0xffffffffu, n, 16);
            if (lane < 4) {
                const int cl = nloc + (q >> 1) * 8 + lane * 2 + (q & 1);
                const int gj = bj + cl;
                atomicAdd(&g_row[gj * 4 + 0], c);
                atomicAdd(&g_row[gj * 4 + 1], t);
                atomicAdd(&g_row[gj * 4 + 3], n);
            }
        }
    }

    // ---- last-block finalize ----
    __syncthreads();
    __shared__ int slast;
    if (tid == 0) {
        __threadfence();
        int o = atomicAdd(&g_done, 1);
        slast = (o == NTILES - 1);
    }
    __syncthreads();
    if (!slast) return;
    __threadfence();

    double sm = 0, tc = 0, acd = 0, psd = 0, nsd = 0;
    for (int i = tid; i < NN; i += 256) {
        float4 r = *reinterpret_cast<const float4*>(g_row + i * 4);
        tc += (double)r.x; psd += (double)r.z; nsd += (double)r.w;
        if (r.x > 0.0f) sm += (double)(r.y / r.x);
        else            acd += 1.0;
    }
    #pragma unroll
    for (int o = 16; o; o >>= 1) {
        sm  += __shfl_xor_sync(0xffffffffu, sm, o);
        tc  += __shfl_xor_sync(0xffffffffu, tc, o);
        acd += __shfl_xor_sync(0xffffffffu, acd, o);
        psd += __shfl_xor_sync(0xffffffffu, psd, o);
        nsd += __shfl_xor_sync(0xffffffffu, nsd, o);
    }
    __shared__ double sh[5][8];
    int w = tid >> 5;
    if ((tid & 31) == 0) { sh[0][w] = sm; sh[1][w] = tc; sh[2][w] = acd; sh[3][w] = psd; sh[4][w] = nsd; }
    __syncthreads();
    if (tid == 0) {
        double Sm = 0, Tc = 0, Ac = 0, Ps = 0, Ns = 0;
        #pragma unroll
        for (int ww = 0; ww < 8; ww++) {
            Sm += sh[0][ww]; Tc += sh[1][ww]; Ac += sh[2][ww]; Ps += sh[3][ww]; Ns += sh[4][ww];
        }
        float loss = (Tc > 0.0) ? (float)(Sm / Tc) : 0.0f;
        if (out_size >= 1) out[0] = loss;
        if (out_size >= 2) out[1] = (float)(Ac / (double)NN);
        if (out_size >= 3) out[2] = (float)(Ps / ((double)NN * (KPC - 1)));
        if (out_size >= 4) out[3] = (float)(Ns / ((double)NN * (NN - KPC)));
    }
    for (int idx = 4 + tid; idx < out_size; idx += 256) out[idx] = 0.0f;
}

// ---------------------------------------------------------------------------
extern "C" void kernel_launch(void* const* d_in, const int* in_sizes, int n_in,
                              void* d_out, int out_size) {
    const float* inputs = (const float*)d_in[0];
    (void)in_sizes; (void)n_in;
    float* out = (float*)d_out;

    cudaFuncSetAttribute(fused_kernel, cudaFuncAttributeMaxDynamicSharedMemorySize, SMEM_TOTAL);
    cudaFuncSetAttribute(fused_kernel, cudaFuncAttributePreferredSharedMemoryCarveout, 100);

    prep_kernel<<<NN / KPC, 256>>>(inputs);
    fused_kernel<<<NTILES, 256, SMEM_TOTAL>>>(out, out_size);
}

// round 10
// speedup vs baseline: 1.2543x; 1.2543x over previous
#include <cuda_runtime.h>
#include <cuda_fp16.h>
#include <cstdint>

#define NN 2048
#define DD 512
#define KPC 8
#define TM 128
#define TN 64
#define KS 64
#define NSLAB (DD / KS)

// ---------------- scratch (no allocations allowed) ----------------
__device__ __half g_xf[NN * DD];             // fp16 normalized (MMA operand)
__device__ float g_sq[NN];
__device__ float g_pos[NN * 8];              // P_k = exp(pos dist), self slot = 0
__device__ float g_thr[NN * 8];              // thr_k = p_k + eps (validity on d)
__device__ float g_row[NN * 4];              // cnt, trip_sum, pos_sum, neg_sum
__device__ int g_done;

// ---------------- helpers ----------------
__device__ __forceinline__ uint32_t smem_to_u32(const void* p) {
    uint32_t a;
    asm("{ .reg .u64 t; cvta.to.shared.u64 t, %1; cvt.u32.u64 %0, t; }" : "=r"(a) : "l"(p));
    return a;
}
__device__ __forceinline__ float fast_exp2(float x) { float y; asm("ex2.approx.f32 %0, %1;" : "=f"(y) : "f"(x)); return y; }
__device__ __forceinline__ float fast_log2(float x) { float y; asm("lg2.approx.f32 %0, %1;" : "=f"(y) : "f"(x)); return y; }
__device__ __forceinline__ float warp_sum(float v) {
    #pragma unroll
    for (int o = 16; o; o >>= 1) v += __shfl_xor_sync(0xffffffffu, v, o);
    return v;
}

#define CPA(dst, src) \
    asm volatile("cp.async.cg.shared.global [%0], [%1], 16;" :: "r"(dst), "l"(src))
#define CPA_COMMIT() asm volatile("cp.async.commit_group;" ::: "memory")

__device__ __forceinline__ void ldm_x4(uint32_t* r, uint32_t addr) {
    asm volatile("ldmatrix.sync.aligned.m8n8.x4.shared.b16 {%0,%1,%2,%3}, [%4];"
                 : "=r"(r[0]), "=r"(r[1]), "=r"(r[2]), "=r"(r[3]) : "r"(addr));
}
__device__ __forceinline__ void mma_fp16(float* c, const uint32_t* a, uint32_t b0, uint32_t b1) {
    asm volatile(
        "mma.sync.aligned.m16n8k16.row.col.f32.f16.f16.f32 "
        "{%0,%1,%2,%3}, {%4,%5,%6,%7}, {%8,%9}, {%0,%1,%2,%3};"
        : "+f"(c[0]), "+f"(c[1]), "+f"(c[2]), "+f"(c[3])
        : "r"(a[0]), "r"(a[1]), "r"(a[2]), "r"(a[3]), "r"(b0), "r"(b1));
}

// ---------------------------------------------------------------------------
// 1) prep: normalize + fp16 + sq + per-class positives (P, thr) + init g_row
// ---------------------------------------------------------------------------
#define XPAD 4
__global__ __launch_bounds__(256) void prep_kernel(const float* __restrict__ in) {
    __shared__ float xs[KPC][DD + XPAD];
    __shared__ float ssq[KPC];
    const int cls = blockIdx.x;
    const int tid = threadIdx.x;
    const int w = tid >> 5;
    const int l = tid & 31;
    const int row = cls * KPC + w;
    if (cls == 0 && tid == 0) g_done = 0;

    float4 v[4];
    const float4* src = reinterpret_cast<const float4*>(in + row * DD) + l * 4;
    #pragma unroll
    for (int q = 0; q < 4; q++) v[q] = src[q];
    float ss = 0.0f;
    #pragma unroll
    for (int q = 0; q < 4; q++)
        ss += v[q].x * v[q].x + v[q].y * v[q].y + v[q].z * v[q].z + v[q].w * v[q].w;
    ss = warp_sum(ss);
    float s = 4.0f * rsqrtf(ss);

    __half2* pf = reinterpret_cast<__half2*>(g_xf + row * DD + l * 16);
    #pragma unroll
    for (int q = 0; q < 4; q++) {
        float4 o4 = make_float4(v[q].x * s, v[q].y * s, v[q].z * s, v[q].w * s);
        xs[w][l * 16 + q * 4 + 0] = o4.x;
        xs[w][l * 16 + q * 4 + 1] = o4.y;
        xs[w][l * 16 + q * 4 + 2] = o4.z;
        xs[w][l * 16 + q * 4 + 3] = o4.w;
        pf[q * 2 + 0] = __half2(__float2half_rn(o4.x), __float2half_rn(o4.y));
        pf[q * 2 + 1] = __half2(__float2half_rn(o4.z), __float2half_rn(o4.w));
    }
    if (l == 0) { g_sq[row] = ss * s * s; ssq[w] = ss * s * s; }
    __syncthreads();

    if (tid < 64) {
        const float L2E = 1.4426950408889634f;
        int a = tid >> 3, b = tid & 7;
        float dot = 0.0f;
        #pragma unroll 4
        for (int q = 0; q < DD; q += 4) {
            dot += xs[a][q + 0] * xs[b][q + 0] + xs[a][q + 1] * xs[b][q + 1]
                 + xs[a][q + 2] * xs[b][q + 2] + xs[a][q + 3] * xs[b][q + 3];
        }
        int ia = cls * KPC + a;
        float p = ssq[a] + ssq[b] - 2.0f * dot;
        bool self = (a == b);
        g_pos[ia * 8 + b] = self ? 0.0f : fast_exp2(p * L2E);
        g_thr[ia * 8 + b] = self ? -1.0e30f : (p + 2.9447e-4f);
        float ps = self ? 0.0f : p;
        ps += __shfl_xor_sync(0xffffffffu, ps, 1);
        ps += __shfl_xor_sync(0xffffffffu, ps, 2);
        ps += __shfl_xor_sync(0xffffffffu, ps, 4);
        if (b == 0) {
            g_row[ia * 4 + 0] = 0.0f;
            g_row[ia * 4 + 1] = 0.0f;
            g_row[ia * 4 + 2] = ps;
            g_row[ia * 4 + 3] = 0.0f;
        }
    }
}

// ---------------------------------------------------------------------------
// 2) fused HMMA Gram (128x64 tile, 512 CTAs) + ILP-restructured epilogue
// ---------------------------------------------------------------------------
#define SM_SQI 0
#define SM_SQJ 512
#define SM_PI  1024
#define SM_THR 5120
#define SM_BUF 9216
#define A_OFF 0
#define B_OFF 16384
#define BUFSZ 24576
#define SMEM_TOTAL (SM_BUF + 2 * BUFSZ)

__device__ __forceinline__ void load_slab_async(uint32_t smb, int buf, int s,
                                                int bi, int bj, int tid) {
    const int k0 = s * KS;
    const uint32_t bufb = smb + SM_BUF + buf * BUFSZ;
    // A: 128 rows x 8 chunks of 16B; 2 threads per row
    {
        const int row = tid >> 1;
        const int cb = (tid & 1) * 4;
        const char* sp = reinterpret_cast<const char*>(g_xf + (bi + row) * DD + k0);
        uint32_t dA = bufb + A_OFF + row * 128;
        #pragma unroll
        for (int c = 0; c < 4; c++) {
            int ch = cb + c;
            CPA(dA + (((ch ^ (row & 7))) << 4), sp + ch * 16);
        }
    }
    // B: 64 rows x 8 chunks; 4 threads per row
    {
        const int row = tid >> 2;
        const int cb = (tid & 3) * 2;
        const char* sp = reinterpret_cast<const char*>(g_xf + (bj + row) * DD + k0);
        uint32_t dB = bufb + B_OFF + row * 128;
        #pragma unroll
        for (int c = 0; c < 2; c++) {
            int ch = cb + c;
            CPA(dB + (((ch ^ (row & 7))) << 4), sp + ch * 16);
        }
    }
}

__global__ __launch_bounds__(256, 3) void fused_kernel(float* __restrict__ out, int out_size) {
    extern __shared__ char smem[];
    const int tid = threadIdx.x;
    const int wid = tid >> 5;
    const int lane = tid & 31;
    const int bi = blockIdx.y * TM;
    const int bj = blockIdx.x * TN;
    const int mloc = (wid >> 1) * 32;    // 4 m-warps of 32 rows
    const int nloc = (wid & 1) * 32;     // 2 n-warps of 32 cols
    const uint32_t smb = smem_to_u32(smem);
    float* sSqi = reinterpret_cast<float*>(smem + SM_SQI);
    float* sSqj = reinterpret_cast<float*>(smem + SM_SQJ);
    float* sPi  = reinterpret_cast<float*>(smem + SM_PI);
    float* sThr = reinterpret_cast<float*>(smem + SM_THR);

    load_slab_async(smb, 0, 0, bi, bj, tid);
    CPA_COMMIT();

    if (tid < 128) sSqi[tid] = g_sq[bi + tid];
    else if (tid < 192) sSqj[tid - 128] = g_sq[bj + (tid - 128)];
    reinterpret_cast<float4*>(sPi)[tid] = reinterpret_cast<const float4*>(g_pos + bi * 8)[tid];
    reinterpret_cast<float4*>(sThr)[tid] = reinterpret_cast<const float4*>(g_thr + bi * 8)[tid];

    float acc[2][4][4];
    #pragma unroll
    for (int mi = 0; mi < 2; mi++)
        #pragma unroll
        for (int ni = 0; ni < 4; ni++)
            #pragma unroll
            for (int r = 0; r < 4; r++) acc[mi][ni][r] = 0.0f;

    const int rA = (lane & 7) + (((lane >> 3) & 1) << 3);
    const int cSel = lane >> 4;
    const int x7 = lane & 7;

    // hoisted swizzle offsets (loop-invariant)
    uint32_t koff[4];
    #pragma unroll
    for (int ks = 0; ks < 4; ks++) koff[ks] = ((uint32_t)((2 * ks + cSel) ^ x7)) << 4;
    const uint32_t arow = (uint32_t)(mloc + rA) * 128;
    const uint32_t brow = (uint32_t)(nloc + rA) * 128;

    #pragma unroll 1
    for (int s = 0; s < NSLAB; s++) {
        const int b = s & 1;
        if (s + 1 < NSLAB) { load_slab_async(smb, 1 - b, s + 1, bi, bj, tid); CPA_COMMIT(); }
        if (s + 1 < NSLAB) asm volatile("cp.async.wait_group 1;" ::: "memory");
        else               asm volatile("cp.async.wait_group 0;" ::: "memory");
        __syncthreads();

        const uint32_t base = smb + SM_BUF + b * BUFSZ;
        const uint32_t baseA = base + A_OFF + arow;
        const uint32_t baseB = base + B_OFF + brow;
        #pragma unroll
        for (int ks = 0; ks < 4; ks++) {
            uint32_t af[2][4];
            ldm_x4(af[0], baseA + koff[ks]);
            ldm_x4(af[1], baseA + 16 * 128 + koff[ks]);
            uint32_t bfr[2][4];
            ldm_x4(bfr[0], baseB + koff[ks]);
            ldm_x4(bfr[1], baseB + 16 * 128 + koff[ks]);
            #pragma unroll
            for (int mi = 0; mi < 2; mi++)
                #pragma unroll
                for (int nt = 0; nt < 2; nt++) {
                    mma_fp16(acc[mi][2 * nt],     af[mi], bfr[nt][0], bfr[nt][2]);
                    mma_fp16(acc[mi][2 * nt + 1], af[mi], bfr[nt][1], bfr[nt][3]);
                }
        }
        __syncthreads();
    }

    // ---- triplet epilogue (ILP-restructured) ----
    const float L2E = 1.4426950408889634f;
    const float LN2 = 0.6931471805599453f;

    // hoist the 8 column sq values used by this thread
    float sqjr[8];
    #pragma unroll
    for (int q = 0; q < 8; q++) {
        const int cl = nloc + (q >> 1) * 8 + (lane & 3) * 2 + (q & 1);
        sqjr[q] = sSqj[cl];
    }

    #pragma unroll
    for (int mi = 0; mi < 2; mi++) {
        #pragma unroll
        for (int h = 0; h < 2; h++) {
            const int rl = mloc + mi * 16 + h * 8 + (lane >> 2);
            const int gi = bi + rl;
            const float sqi = sSqi[rl];
            const float4 p0 = *reinterpret_cast<const float4*>(sPi + rl * 8);
            const float4 p1 = *reinterpret_cast<const float4*>(sPi + rl * 8 + 4);
            const float4 t0 = *reinterpret_cast<const float4*>(sThr + rl * 8);
            const float4 t1 = *reinterpret_cast<const float4*>(sThr + rl * 8 + 4);
            const int skipni = ((gi >> 3) - (bj >> 3)) - (nloc >> 3);

            float sqs[8];
            #pragma unroll
            for (int q = 0; q < 8; q++) sqs[q] = sqi + sqjr[q];

            int ic0 = 0, ic1 = 0;
            float tr0 = 0.0f, tr1 = 0.0f;
            float ng0 = 0.0f, ng1 = 0.0f;
            #pragma unroll
            for (int ni = 0; ni < 4; ni++) {
                if (ni == skipni) continue;
                #pragma unroll
                for (int rr = 0; rr < 2; rr++) {
                    const int q = ni * 2 + rr;
                    const float d = fmaf(-2.0f, acc[mi][ni][h * 2 + rr], sqs[q]);
                    const float en = fast_exp2(-d * L2E);
                    const bool v0 = d < t0.x, v1 = d < t0.y, v2 = d < t0.z, v3 = d < t0.w;
                    const bool v4 = d < t1.x, v5 = d < t1.y, v6 = d < t1.z, v7 = d < t1.w;
                    // integer counts on ALU pipe, two independent partials
                    ic0 += (int)v0 + (int)v1 + (int)v2 + (int)v3;
                    ic1 += (int)v4 + (int)v5 + (int)v6 + (int)v7;
                    // tree products, two independent chains
                    float a0 = (v0 ? fmaf(p0.x, en, 1.0f) : 1.0f) * (v1 ? fmaf(p0.y, en, 1.0f) : 1.0f);
                    float a1 = (v2 ? fmaf(p0.z, en, 1.0f) : 1.0f) * (v3 ? fmaf(p0.w, en, 1.0f) : 1.0f);
                    float b0 = (v4 ? fmaf(p1.x, en, 1.0f) : 1.0f) * (v5 ? fmaf(p1.y, en, 1.0f) : 1.0f);
                    float b1 = (v6 ? fmaf(p1.z, en, 1.0f) : 1.0f) * (v7 ? fmaf(p1.w, en, 1.0f) : 1.0f);
                    tr0 += fast_log2(a0 * a1);
                    tr1 += fast_log2(b0 * b1);
                    if (rr == 0) ng0 += d; else ng1 += d;
                }
            }
            float cnt = (float)(ic0 + ic1);
            float trip = LN2 * (tr0 + tr1);
            float neg = ng0 + ng1;

            cnt  += __shfl_xor_sync(0xffffffffu, cnt, 1);
            cnt  += __shfl_xor_sync(0xffffffffu, cnt, 2);
            trip += __shfl_xor_sync(0xffffffffu, trip, 1);
            trip += __shfl_xor_sync(0xffffffffu, trip, 2);
            neg  += __shfl_xor_sync(0xffffffffu, neg, 1);
            neg  += __shfl_xor_sync(0xffffffffu, neg, 2);
            if ((lane & 3) == 0) {
                atomicAdd(&g_row[gi * 4 + 0], cnt);
                atomicAdd(&g_row[gi * 4 + 1], trip);
                atomicAdd(&g_row[gi * 4 + 3], neg);
            }
        }
    }

    // ---- last-block finalize ----
    __syncthreads();
    __shared__ int slast;
    if (tid == 0) {
        __threadfence();
        int o = atomicAdd(&g_done, 1);
        slast = (o == (int)(gridDim.x * gridDim.y) - 1);
    }
    __syncthreads();
    if (!slast) return;
    __threadfence();

    double sm = 0, tc = 0, acd = 0, psd = 0, nsd = 0;
    for (int i = tid; i < NN; i += 256) {
        float4 r = *reinterpret_cast<const float4*>(g_row + i * 4);
        tc += (double)r.x; psd += (double)r.z; nsd += (double)r.w;
        if (r.x > 0.0f) sm += (double)(r.y / r.x);
        else            acd += 1.0;
    }
    #pragma unroll
    for (int o = 16; o; o >>= 1) {
        sm  += __shfl_xor_sync(0xffffffffu, sm, o);
        tc  += __shfl_xor_sync(0xffffffffu, tc, o);
        acd += __shfl_xor_sync(0xffffffffu, acd, o);
        psd += __shfl_xor_sync(0xffffffffu, psd, o);
        nsd += __shfl_xor_sync(0xffffffffu, nsd, o);
    }
    __shared__ double sh[5][8];
    int w = tid >> 5;
    if ((tid & 31) == 0) { sh[0][w] = sm; sh[1][w] = tc; sh[2][w] = acd; sh[3][w] = psd; sh[4][w] = nsd; }
    __syncthreads();
    if (tid == 0) {
        double Sm = 0, Tc = 0, Ac = 0, Ps = 0, Ns = 0;
        #pragma unroll
        for (int ww = 0; ww < 8; ww++) {
            Sm += sh[0][ww]; Tc += sh[1][ww]; Ac += sh[2][ww]; Ps += sh[3][ww]; Ns += sh[4][ww];
        }
        float loss = (Tc > 0.0) ? (float)(Sm / Tc) : 0.0f;
        if (out_size >= 1) out[0] = loss;
        if (out_size >= 2) out[1] = (float)(Ac / (double)NN);
        if (out_size >= 3) out[2] = (float)(Ps / ((double)NN * (KPC - 1)));
        if (out_size >= 4) out[3] = (float)(Ns / ((double)NN * (NN - KPC)));
    }
    for (int idx = 4 + tid; idx < out_size; idx += 256) out[idx] = 0.0f;
}

// ---------------------------------------------------------------------------
extern "C" void kernel_launch(void* const* d_in, const int* in_sizes, int n_in,
                              void* d_out, int out_size) {
    const float* inputs = (const float*)d_in[0];
    (void)in_sizes; (void)n_in;
    float* out = (float*)d_out;

    cudaFuncSetAttribute(fused_kernel, cudaFuncAttributeMaxDynamicSharedMemorySize, SMEM_TOTAL);
    cudaFuncSetAttribute(fused_kernel, cudaFuncAttributePreferredSharedMemoryCarveout, 100);

    prep_kernel<<<NN / KPC, 256>>>(inputs);
    fused_kernel<<<dim3(NN / TN, NN / TM), 256, SMEM_TOTAL>>>(out, out_size);
}

// round 11
// speedup vs baseline: 1.3310x; 1.0612x over previous
#include <cuda_runtime.h>
#include <cuda_fp16.h>
#include <cstdint>

#define NN 2048
#define DD 512
#define KPC 8
#define TM 128
#define TN 128
#define KS 64
#define NSLAB (DD / KS)

// ---------------- scratch (no allocations allowed) ----------------
__device__ __half g_xf[NN * DD];             // fp16 normalized (MMA operand)
__device__ float g_sq[NN];
__device__ float g_pos[NN * 8];              // P_k = exp(pos dist), self slot = 0
__device__ float g_thr[NN * 8];              // thr_k = p_k + eps (validity on d)
__device__ float g_dist[(size_t)NN * NN];    // 16 MB distance matrix
__device__ float g_row[NN * 4];              // cnt, trip_sum, pos_sum, neg_sum
__device__ int g_done;

// ---------------- helpers ----------------
__device__ __forceinline__ uint32_t smem_to_u32(const void* p) {
    uint32_t a;
    asm("{ .reg .u64 t; cvta.to.shared.u64 t, %1; cvt.u32.u64 %0, t; }" : "=r"(a) : "l"(p));
    return a;
}
__device__ __forceinline__ float fast_exp2(float x) { float y; asm("ex2.approx.f32 %0, %1;" : "=f"(y) : "f"(x)); return y; }
__device__ __forceinline__ float fast_log2(float x) { float y; asm("lg2.approx.f32 %0, %1;" : "=f"(y) : "f"(x)); return y; }
__device__ __forceinline__ float warp_sum(float v) {
    #pragma unroll
    for (int o = 16; o; o >>= 1) v += __shfl_xor_sync(0xffffffffu, v, o);
    return v;
}

#define CPA(dst, src) \
    asm volatile("cp.async.cg.shared.global [%0], [%1], 16;" :: "r"(dst), "l"(src))
#define CPA_COMMIT() asm volatile("cp.async.commit_group;" ::: "memory")

__device__ __forceinline__ void ldm_x4(uint32_t* r, uint32_t addr) {
    asm volatile("ldmatrix.sync.aligned.m8n8.x4.shared.b16 {%0,%1,%2,%3}, [%4];"
                 : "=r"(r[0]), "=r"(r[1]), "=r"(r[2]), "=r"(r[3]) : "r"(addr));
}
__device__ __forceinline__ void mma_fp16(float* c, const uint32_t* a, uint32_t b0, uint32_t b1) {
    asm volatile(
        "mma.sync.aligned.m16n8k16.row.col.f32.f16.f16.f32 "
        "{%0,%1,%2,%3}, {%4,%5,%6,%7}, {%8,%9}, {%0,%1,%2,%3};"
        : "+f"(c[0]), "+f"(c[1]), "+f"(c[2]), "+f"(c[3])
        : "r"(a[0]), "r"(a[1]), "r"(a[2]), "r"(a[3]), "r"(b0), "r"(b1));
}

// ---------------------------------------------------------------------------
// 1) prep: normalize + fp16 + sq + per-class positives (P, thr) + init g_row
// ---------------------------------------------------------------------------
#define XPAD 4
__global__ __launch_bounds__(256) void prep_kernel(const float* __restrict__ in) {
    __shared__ float xs[KPC][DD + XPAD];
    __shared__ float ssq[KPC];
    const int cls = blockIdx.x;
    const int tid = threadIdx.x;
    const int w = tid >> 5;
    const int l = tid & 31;
    const int row = cls * KPC + w;
    if (cls == 0 && tid == 0) g_done = 0;

    float4 v[4];
    const float4* src = reinterpret_cast<const float4*>(in + row * DD) + l * 4;
    #pragma unroll
    for (int q = 0; q < 4; q++) v[q] = src[q];
    float ss = 0.0f;
    #pragma unroll
    for (int q = 0; q < 4; q++)
        ss += v[q].x * v[q].x + v[q].y * v[q].y + v[q].z * v[q].z + v[q].w * v[q].w;
    ss = warp_sum(ss);
    float s = 4.0f * rsqrtf(ss);

    __half2* pf = reinterpret_cast<__half2*>(g_xf + row * DD + l * 16);
    #pragma unroll
    for (int q = 0; q < 4; q++) {
        float4 o4 = make_float4(v[q].x * s, v[q].y * s, v[q].z * s, v[q].w * s);
        xs[w][l * 16 + q * 4 + 0] = o4.x;
        xs[w][l * 16 + q * 4 + 1] = o4.y;
        xs[w][l * 16 + q * 4 + 2] = o4.z;
        xs[w][l * 16 + q * 4 + 3] = o4.w;
        pf[q * 2 + 0] = __half2(__float2half_rn(o4.x), __float2half_rn(o4.y));
        pf[q * 2 + 1] = __half2(__float2half_rn(o4.z), __float2half_rn(o4.w));
    }
    if (l == 0) { g_sq[row] = ss * s * s; ssq[w] = ss * s * s; }
    __syncthreads();

    if (tid < 64) {
        const float L2E = 1.4426950408889634f;
        int a = tid >> 3, b = tid & 7;
        float dot = 0.0f;
        #pragma unroll 4
        for (int q = 0; q < DD; q += 4) {
            dot += xs[a][q + 0] * xs[b][q + 0] + xs[a][q + 1] * xs[b][q + 1]
                 + xs[a][q + 2] * xs[b][q + 2] + xs[a][q + 3] * xs[b][q + 3];
        }
        int ia = cls * KPC + a;
        float p = ssq[a] + ssq[b] - 2.0f * dot;
        bool self = (a == b);
        g_pos[ia * 8 + b] = self ? 0.0f : fast_exp2(p * L2E);
        g_thr[ia * 8 + b] = self ? -1.0e30f : (p + 2.9447e-4f);
        float ps = self ? 0.0f : p;
        ps += __shfl_xor_sync(0xffffffffu, ps, 1);
        ps += __shfl_xor_sync(0xffffffffu, ps, 2);
        ps += __shfl_xor_sync(0xffffffffu, ps, 4);
        if (b == 0) g_row[ia * 4 + 2] = ps;
    }
}

// ---------------------------------------------------------------------------
// 2) gemm_kernel: pure HMMA Gram, stores d = sqi+sqj-2*dot to g_dist
//    tile 128x128, grid 256 (single wave at occ 2)
// ---------------------------------------------------------------------------
#define SM_SQI 0
#define SM_SQJ 512
#define SM_BUF 1024
#define A_OFF 0
#define B_OFF 16384
#define BUFSZ 32768
#define SMEM_TOTAL (SM_BUF + 2 * BUFSZ)

__device__ __forceinline__ void load_slab_async(uint32_t smb, int buf, int s,
                                                int bi, int bj, int tid) {
    const int k0 = s * KS;
    const uint32_t bufb = smb + SM_BUF + buf * BUFSZ;
    const int row = tid >> 1;
    const int cb = (tid & 1) * 4;
    // A: 128 rows x 8 chunks of 16B; 2 threads per row
    {
        const char* sp = reinterpret_cast<const char*>(g_xf + (bi + row) * DD + k0);
        uint32_t dA = bufb + A_OFF + row * 128;
        #pragma unroll
        for (int c = 0; c < 4; c++) {
            int ch = cb + c;
            CPA(dA + (((ch ^ (row & 7))) << 4), sp + ch * 16);
        }
    }
    // B: 128 rows x 8 chunks; 2 threads per row
    {
        const char* sp = reinterpret_cast<const char*>(g_xf + (bj + row) * DD + k0);
        uint32_t dB = bufb + B_OFF + row * 128;
        #pragma unroll
        for (int c = 0; c < 4; c++) {
            int ch = cb + c;
            CPA(dB + (((ch ^ (row & 7))) << 4), sp + ch * 16);
        }
    }
}

__global__ __launch_bounds__(256, 2) void gemm_kernel() {
    extern __shared__ char smem[];
    const int tid = threadIdx.x;
    const int wid = tid >> 5;
    const int lane = tid & 31;
    const int bi = blockIdx.y * TM;
    const int bj = blockIdx.x * TN;
    const int mloc = (wid >> 2) * 64;    // 2 m-warps of 64 rows
    const int nloc = (wid & 3) * 32;     // 4 n-warps of 32 cols
    const uint32_t smb = smem_to_u32(smem);
    float* sSqi = reinterpret_cast<float*>(smem + SM_SQI);
    float* sSqj = reinterpret_cast<float*>(smem + SM_SQJ);

    load_slab_async(smb, 0, 0, bi, bj, tid);
    CPA_COMMIT();

    if (tid < 128) sSqi[tid] = g_sq[bi + tid];
    else           sSqj[tid - 128] = g_sq[bj + (tid - 128)];

    float acc[4][4][4];
    #pragma unroll
    for (int mi = 0; mi < 4; mi++)
        #pragma unroll
        for (int ni = 0; ni < 4; ni++)
            #pragma unroll
            for (int r = 0; r < 4; r++) acc[mi][ni][r] = 0.0f;

    const int rA = (lane & 7) + (((lane >> 3) & 1) << 3);
    const int cSel = lane >> 4;
    const int x7 = lane & 7;
    uint32_t koff[4];
    #pragma unroll
    for (int ks = 0; ks < 4; ks++) koff[ks] = ((uint32_t)((2 * ks + cSel) ^ x7)) << 4;
    const uint32_t arow = (uint32_t)(mloc + rA) * 128;
    const uint32_t brow = (uint32_t)(nloc + rA) * 128;

    #pragma unroll 1
    for (int s = 0; s < NSLAB; s++) {
        const int b = s & 1;
        if (s + 1 < NSLAB) { load_slab_async(smb, 1 - b, s + 1, bi, bj, tid); CPA_COMMIT(); }
        if (s + 1 < NSLAB) asm volatile("cp.async.wait_group 1;" ::: "memory");
        else               asm volatile("cp.async.wait_group 0;" ::: "memory");
        __syncthreads();

        const uint32_t base = smb + SM_BUF + b * BUFSZ;
        const uint32_t baseA = base + A_OFF + arow;
        const uint32_t baseB = base + B_OFF + brow;
        #pragma unroll
        for (int ks = 0; ks < 4; ks++) {
            uint32_t af[4][4];
            #pragma unroll
            for (int mi = 0; mi < 4; mi++) ldm_x4(af[mi], baseA + mi * (16 * 128) + koff[ks]);
            uint32_t bfr[2][4];
            #pragma unroll
            for (int nt = 0; nt < 2; nt++) ldm_x4(bfr[nt], baseB + nt * (16 * 128) + koff[ks]);
            #pragma unroll
            for (int mi = 0; mi < 4; mi++)
                #pragma unroll
                for (int nt = 0; nt < 2; nt++) {
                    mma_fp16(acc[mi][2 * nt],     af[mi], bfr[nt][0], bfr[nt][2]);
                    mma_fp16(acc[mi][2 * nt + 1], af[mi], bfr[nt][1], bfr[nt][3]);
                }
        }
        __syncthreads();
    }

    // store d = sqi + sqj - 2*dot as float2 pairs
    #pragma unroll
    for (int mi = 0; mi < 4; mi++) {
        #pragma unroll
        for (int h = 0; h < 2; h++) {
            const int rl = mloc + mi * 16 + h * 8 + (lane >> 2);
            const float sqi = sSqi[rl];
            float* drow = g_dist + (size_t)(bi + rl) * NN + bj;
            #pragma unroll
            for (int ni = 0; ni < 4; ni++) {
                const int cl = nloc + ni * 8 + (lane & 3) * 2;
                float2 o;
                o.x = fmaf(-2.0f, acc[mi][ni][h * 2 + 0], sqi + sSqj[cl]);
                o.y = fmaf(-2.0f, acc[mi][ni][h * 2 + 1], sqi + sSqj[cl + 1]);
                *reinterpret_cast<float2*>(drow + cl) = o;
            }
        }
    }
}

// ---------------------------------------------------------------------------
// 3) triplet_kernel: one CTA per row, no atomics, fused last-block finalize
// ---------------------------------------------------------------------------
__global__ __launch_bounds__(256) void triplet_kernel(float* __restrict__ out, int out_size) {
    const int row = blockIdx.x;
    const int cls = row >> 3;
    const int tid = threadIdx.x;
    const float L2E = 1.4426950408889634f;
    const float LN2 = 0.6931471805599453f;

    // broadcast row constants
    __shared__ float sP[8], sT[8];
    if (tid < 8) { sP[tid] = g_pos[row * 8 + tid]; sT[tid] = g_thr[row * 8 + tid]; }
    __syncthreads();
    const float4 p0 = *reinterpret_cast<const float4*>(sP);
    const float4 p1 = *reinterpret_cast<const float4*>(sP + 4);
    const float4 t0 = *reinterpret_cast<const float4*>(sT);
    const float4 t1 = *reinterpret_cast<const float4*>(sT + 4);

    const float* drow = g_dist + (size_t)row * NN;
    int ic = 0;
    float tr = 0.0f, ng = 0.0f;

    #pragma unroll
    for (int half = 0; half < 2; half++) {
        const int j0 = half * 1024 + tid * 4;
        const float4 dv = *reinterpret_cast<const float4*>(drow + j0);
        const float dd[4] = { dv.x, dv.y, dv.z, dv.w };
        #pragma unroll
        for (int q = 0; q < 4; q++) {
            const int j = j0 + q;
            if ((j >> 3) == cls) continue;
            const float d = dd[q];
            ng += d;
            const float en = fast_exp2(-d * L2E);
            const bool v0 = d < t0.x, v1 = d < t0.y, v2 = d < t0.z, v3 = d < t0.w;
            const bool v4 = d < t1.x, v5 = d < t1.y, v6 = d < t1.z, v7 = d < t1.w;
            ic += (int)v0 + (int)v1 + (int)v2 + (int)v3
                + (int)v4 + (int)v5 + (int)v6 + (int)v7;
            float a0 = (v0 ? fmaf(p0.x, en, 1.0f) : 1.0f) * (v1 ? fmaf(p0.y, en, 1.0f) : 1.0f);
            float a1 = (v2 ? fmaf(p0.z, en, 1.0f) : 1.0f) * (v3 ? fmaf(p0.w, en, 1.0f) : 1.0f);
            float b0 = (v4 ? fmaf(p1.x, en, 1.0f) : 1.0f) * (v5 ? fmaf(p1.y, en, 1.0f) : 1.0f);
            float b1 = (v6 ? fmaf(p1.z, en, 1.0f) : 1.0f) * (v7 ? fmaf(p1.w, en, 1.0f) : 1.0f);
            tr += fast_log2(a0 * a1) + fast_log2(b0 * b1);
        }
    }

    float cnt = (float)ic;
    float trip = LN2 * tr;
    cnt  = warp_sum(cnt);
    trip = warp_sum(trip);
    ng   = warp_sum(ng);
    __shared__ float r0[8], r1[8], r2[8];
    const int w = tid >> 5;
    if ((tid & 31) == 0) { r0[w] = cnt; r1[w] = trip; r2[w] = ng; }
    __syncthreads();
    if (tid == 0) {
        float c = 0, t = 0, n = 0;
        #pragma unroll
        for (int ww = 0; ww < 8; ww++) { c += r0[ww]; t += r1[ww]; n += r2[ww]; }
        g_row[row * 4 + 0] = c;
        g_row[row * 4 + 1] = t;
        g_row[row * 4 + 3] = n;
    }

    // ---- last-block finalize ----
    __syncthreads();
    __shared__ int slast;
    if (tid == 0) {
        __threadfence();
        int o = atomicAdd(&g_done, 1);
        slast = (o == NN - 1);
    }
    __syncthreads();
    if (!slast) return;
    __threadfence();

    double sm = 0, tc = 0, acd = 0, psd = 0, nsd = 0;
    for (int i = tid; i < NN; i += 256) {
        float4 r = *reinterpret_cast<const float4*>(g_row + i * 4);
        tc += (double)r.x; psd += (double)r.z; nsd += (double)r.w;
        if (r.x > 0.0f) sm += (double)(r.y / r.x);
        else            acd += 1.0;
    }
    #pragma unroll
    for (int o = 16; o; o >>= 1) {
        sm  += __shfl_xor_sync(0xffffffffu, sm, o);
        tc  += __shfl_xor_sync(0xffffffffu, tc, o);
        acd += __shfl_xor_sync(0xffffffffu, acd, o);
        psd += __shfl_xor_sync(0xffffffffu, psd, o);
        nsd += __shfl_xor_sync(0xffffffffu, nsd, o);
    }
    __shared__ double sh[5][8];
    if ((tid & 31) == 0) { sh[0][w] = sm; sh[1][w] = tc; sh[2][w] = acd; sh[3][w] = psd; sh[4][w] = nsd; }
    __syncthreads();
    if (tid == 0) {
        double Sm = 0, Tc = 0, Ac = 0, Ps = 0, Ns = 0;
        #pragma unroll
        for (int ww = 0; ww < 8; ww++) {
            Sm += sh[0][ww]; Tc += sh[1][ww]; Ac += sh[2][ww]; Ps += sh[3][ww]; Ns += sh[4][ww];
        }
        float loss = (Tc > 0.0) ? (float)(Sm / Tc) : 0.0f;
        if (out_size >= 1) out[0] = loss;
        if (out_size >= 2) out[1] = (float)(Ac / (double)NN);
        if (out_size >= 3) out[2] = (float)(Ps / ((double)NN * (KPC - 1)));
        if (out_size >= 4) out[3] = (float)(Ns / ((double)NN * (NN - KPC)));
    }
    for (int idx = 4 + tid; idx < out_size; idx += 256) out[idx] = 0.0f;
}

// ---------------------------------------------------------------------------
extern "C" void kernel_launch(void* const* d_in, const int* in_sizes, int n_in,
                              void* d_out, int out_size) {
    const float* inputs = (const float*)d_in[0];
    (void)in_sizes; (void)n_in;
    float* out = (float*)d_out;

    cudaFuncSetAttribute(gemm_kernel, cudaFuncAttributeMaxDynamicSharedMemorySize, SMEM_TOTAL);
    cudaFuncSetAttribute(gemm_kernel, cudaFuncAttributePreferredSharedMemoryCarveout, 100);

    prep_kernel<<<NN / KPC, 256>>>(inputs);
    gemm_kernel<<<dim3(NN / TN, NN / TM), 256, SMEM_TOTAL>>>();
    triplet_kernel<<<NN, 256>>>(out, out_size);
}

// round 12
// speedup vs baseline: 1.3464x; 1.0116x over previous
#include <cuda_runtime.h>
#include <cuda_fp16.h>
#include <cstdint>

#define NN 2048
#define DD 512
#define KPC 8
#define TM 128
#define TN 128
#define KS 64
#define NSLAB (DD / KS)
#define NGEMM 136          // 16*17/2 upper-triangular tiles

// ---------------- scratch (no allocations allowed) ----------------
__device__ __half g_xf[NN * DD];             // fp16 normalized (MMA operand)
__device__ float g_sq[NN];
__device__ float g_pos[NN * 8];              // P_k = exp(pos dist), self slot = 0
__device__ float g_thr[NN * 8];              // thr_k = p_k + eps (validity on d)
__device__ float g_dist[(size_t)NN * NN];    // 16 MB distance matrix
__device__ float g_row[NN * 4];              // cnt, trip_sum, pos_sum, neg_sum
__device__ int g_done;

// ---------------- helpers ----------------
__device__ __forceinline__ uint32_t smem_to_u32(const void* p) {
    uint32_t a;
    asm("{ .reg .u64 t; cvta.to.shared.u64 t, %1; cvt.u32.u64 %0, t; }" : "=r"(a) : "l"(p));
    return a;
}
__device__ __forceinline__ float fast_exp2(float x) { float y; asm("ex2.approx.f32 %0, %1;" : "=f"(y) : "f"(x)); return y; }
__device__ __forceinline__ float fast_log2(float x) { float y; asm("lg2.approx.f32 %0, %1;" : "=f"(y) : "f"(x)); return y; }
__device__ __forceinline__ float warp_sum(float v) {
    #pragma unroll
    for (int o = 16; o; o >>= 1) v += __shfl_xor_sync(0xffffffffu, v, o);
    return v;
}

#define CPA(dst, src) \
    asm volatile("cp.async.cg.shared.global [%0], [%1], 16;" :: "r"(dst), "l"(src))
#define CPA_COMMIT() asm volatile("cp.async.commit_group;" ::: "memory")

__device__ __forceinline__ void ldm_x4(uint32_t* r, uint32_t addr) {
    asm volatile("ldmatrix.sync.aligned.m8n8.x4.shared.b16 {%0,%1,%2,%3}, [%4];"
                 : "=r"(r[0]), "=r"(r[1]), "=r"(r[2]), "=r"(r[3]) : "r"(addr));
}
__device__ __forceinline__ void mma_fp16(float* c, const uint32_t* a, uint32_t b0, uint32_t b1) {
    asm volatile(
        "mma.sync.aligned.m16n8k16.row.col.f32.f16.f16.f32 "
        "{%0,%1,%2,%3}, {%4,%5,%6,%7}, {%8,%9}, {%0,%1,%2,%3};"
        : "+f"(c[0]), "+f"(c[1]), "+f"(c[2]), "+f"(c[3])
        : "r"(a[0]), "r"(a[1]), "r"(a[2]), "r"(a[3]), "r"(b0), "r"(b1));
}

// ---------------------------------------------------------------------------
// 1) prep: normalize + fp16 + sq + per-class positives (P, thr), all threads
// ---------------------------------------------------------------------------
#define XPAD 4
__global__ __launch_bounds__(256) void prep_kernel(const float* __restrict__ in) {
    __shared__ float xs[KPC][DD + XPAD];
    __shared__ float ssq[KPC];
    const int cls = blockIdx.x;
    const int tid = threadIdx.x;
    const int w = tid >> 5;
    const int l = tid & 31;
    const int row = cls * KPC + w;
    if (cls == 0 && tid == 0) g_done = 0;

    float4 v[4];
    const float4* src = reinterpret_cast<const float4*>(in + row * DD) + l * 4;
    #pragma unroll
    for (int q = 0; q < 4; q++) v[q] = src[q];
    float ss = 0.0f;
    #pragma unroll
    for (int q = 0; q < 4; q++)
        ss += v[q].x * v[q].x + v[q].y * v[q].y + v[q].z * v[q].z + v[q].w * v[q].w;
    ss = warp_sum(ss);
    float s = 4.0f * rsqrtf(ss);

    __half2* pf = reinterpret_cast<__half2*>(g_xf + row * DD + l * 16);
    #pragma unroll
    for (int q = 0; q < 4; q++) {
        float4 o4 = make_float4(v[q].x * s, v[q].y * s, v[q].z * s, v[q].w * s);
        xs[w][l * 16 + q * 4 + 0] = o4.x;
        xs[w][l * 16 + q * 4 + 1] = o4.y;
        xs[w][l * 16 + q * 4 + 2] = o4.z;
        xs[w][l * 16 + q * 4 + 3] = o4.w;
        pf[q * 2 + 0] = __half2(__float2half_rn(o4.x), __float2half_rn(o4.y));
        pf[q * 2 + 1] = __half2(__float2half_rn(o4.z), __float2half_rn(o4.w));
    }
    if (l == 0) { g_sq[row] = ss * s * s; ssq[w] = ss * s * s; }
    __syncthreads();

    // 8x8 intra-class dots: 4 threads per pair, 128 dims each
    {
        const float L2E = 1.4426950408889634f;
        const int pair = tid >> 2;     // 0..63; warp w holds a = w, b = 0..7
        const int part = tid & 3;
        const int a = pair >> 3, b = pair & 7;
        const float4* xa4 = reinterpret_cast<const float4*>(&xs[a][part * 128]);
        const float4* xb4 = reinterpret_cast<const float4*>(&xs[b][part * 128]);
        float dot = 0.0f;
        #pragma unroll 8
        for (int q = 0; q < 32; q++) {
            float4 u = xa4[q], vv = xb4[q];
            dot += u.x * vv.x + u.y * vv.y + u.z * vv.z + u.w * vv.w;
        }
        dot += __shfl_xor_sync(0xffffffffu, dot, 1);
        dot += __shfl_xor_sync(0xffffffffu, dot, 2);
        const int ia = cls * KPC + a;
        const float p = ssq[a] + ssq[b] - 2.0f * dot;
        const bool self = (a == b);
        if (part == 0) {
            g_pos[ia * 8 + b] = self ? 0.0f : fast_exp2(p * L2E);
            g_thr[ia * 8 + b] = self ? -1.0e30f : (p + 2.9447e-4f);
        }
        float ps = self ? 0.0f : p;
        ps += __shfl_xor_sync(0xffffffffu, ps, 4);
        ps += __shfl_xor_sync(0xffffffffu, ps, 8);
        ps += __shfl_xor_sync(0xffffffffu, ps, 16);
        if ((tid & 31) == 0) g_row[ia * 4 + 2] = ps;
    }
}

// ---------------------------------------------------------------------------
// 2) gemm_kernel: symmetric HMMA Gram, 136 upper-tri 128x128 tiles.
//    Off-diagonal tiles also store the transposed copy (smem-staged).
// ---------------------------------------------------------------------------
#define SM_SQI 0
#define SM_SQJ 512
#define SM_BUF 1024
#define A_OFF 0
#define B_OFF 16384
#define BUFSZ 32768
#define TSTRIDE 132
#define SMEM_TOTAL (SM_BUF + TM * TSTRIDE * 4)   // 68608 > mainloop's 66560

__device__ __forceinline__ void load_slab_async(uint32_t smb, int buf, int s,
                                                int bi, int bj, int tid) {
    const int k0 = s * KS;
    const uint32_t bufb = smb + SM_BUF + buf * BUFSZ;
    const int row = tid >> 1;
    const int cb = (tid & 1) * 4;
    {
        const char* sp = reinterpret_cast<const char*>(g_xf + (bi + row) * DD + k0);
        uint32_t dA = bufb + A_OFF + row * 128;
        #pragma unroll
        for (int c = 0; c < 4; c++) {
            int ch = cb + c;
            CPA(dA + (((ch ^ (row & 7))) << 4), sp + ch * 16);
        }
    }
    {
        const char* sp = reinterpret_cast<const char*>(g_xf + (bj + row) * DD + k0);
        uint32_t dB = bufb + B_OFF + row * 128;
        #pragma unroll
        for (int c = 0; c < 4; c++) {
            int ch = cb + c;
            CPA(dB + (((ch ^ (row & 7))) << 4), sp + ch * 16);
        }
    }
}

__global__ __launch_bounds__(256, 2) void gemm_kernel() {
    extern __shared__ char smem[];
    const int tid = threadIdx.x;
    const int wid = tid >> 5;
    const int lane = tid & 31;

    // decode upper-triangular tile (ti <= tj)
    int ti = 0, r = blockIdx.x, c = 16;
    while (r >= c) { r -= c; c--; ti++; }
    const int tj = ti + r;
    const int bi = ti * TM;
    const int bj = tj * TN;

    const int mloc = (wid >> 2) * 64;
    const int nloc = (wid & 3) * 32;
    const uint32_t smb = smem_to_u32(smem);
    float* sSqi = reinterpret_cast<float*>(smem + SM_SQI);
    float* sSqj = reinterpret_cast<float*>(smem + SM_SQJ);

    load_slab_async(smb, 0, 0, bi, bj, tid);
    CPA_COMMIT();

    if (tid < 128) sSqi[tid] = g_sq[bi + tid];
    else           sSqj[tid - 128] = g_sq[bj + (tid - 128)];

    float acc[4][4][4];
    #pragma unroll
    for (int mi = 0; mi < 4; mi++)
        #pragma unroll
        for (int ni = 0; ni < 4; ni++)
            #pragma unroll
            for (int rr = 0; rr < 4; rr++) acc[mi][ni][rr] = 0.0f;

    const int rA = (lane & 7) + (((lane >> 3) & 1) << 3);
    const int cSel = lane >> 4;
    const int x7 = lane & 7;
    uint32_t koff[4];
    #pragma unroll
    for (int ks = 0; ks < 4; ks++) koff[ks] = ((uint32_t)((2 * ks + cSel) ^ x7)) << 4;
    const uint32_t arow = (uint32_t)(mloc + rA) * 128;
    const uint32_t brow = (uint32_t)(nloc + rA) * 128;

    #pragma unroll 1
    for (int s = 0; s < NSLAB; s++) {
        const int b = s & 1;
        if (s + 1 < NSLAB) { load_slab_async(smb, 1 - b, s + 1, bi, bj, tid); CPA_COMMIT(); }
        if (s + 1 < NSLAB) asm volatile("cp.async.wait_group 1;" ::: "memory");
        else               asm volatile("cp.async.wait_group 0;" ::: "memory");
        __syncthreads();

        const uint32_t base = smb + SM_BUF + b * BUFSZ;
        const uint32_t baseA = base + A_OFF + arow;
        const uint32_t baseB = base + B_OFF + brow;
        #pragma unroll
        for (int ks = 0; ks < 4; ks++) {
            uint32_t af[4][4];
            #pragma unroll
            for (int mi = 0; mi < 4; mi++) ldm_x4(af[mi], baseA + mi * (16 * 128) + koff[ks]);
            uint32_t bfr[2][4];
            #pragma unroll
            for (int nt = 0; nt < 2; nt++) ldm_x4(bfr[nt], baseB + nt * (16 * 128) + koff[ks]);
            #pragma unroll
            for (int mi = 0; mi < 4; mi++)
                #pragma unroll
                for (int nt = 0; nt < 2; nt++) {
                    mma_fp16(acc[mi][2 * nt],     af[mi], bfr[nt][0], bfr[nt][2]);
                    mma_fp16(acc[mi][2 * nt + 1], af[mi], bfr[nt][1], bfr[nt][3]);
                }
        }
        __syncthreads();
    }

    // normal-orientation store: d = sqi + sqj - 2*dot
    #pragma unroll
    for (int mi = 0; mi < 4; mi++) {
        #pragma unroll
        for (int h = 0; h < 2; h++) {
            const int rl = mloc + mi * 16 + h * 8 + (lane >> 2);
            const float sqi = sSqi[rl];
            float* drow = g_dist + (size_t)(bi + rl) * NN + bj;
            #pragma unroll
            for (int ni = 0; ni < 4; ni++) {
                const int cl = nloc + ni * 8 + (lane & 3) * 2;
                float2 o;
                o.x = fmaf(-2.0f, acc[mi][ni][h * 2 + 0], sqi + sSqj[cl]);
                o.y = fmaf(-2.0f, acc[mi][ni][h * 2 + 1], sqi + sSqj[cl + 1]);
                *reinterpret_cast<float2*>(drow + cl) = o;
            }
        }
    }

    // transposed copy for off-diagonal tiles, staged through smem for coalescing
    if (ti != tj) {
        float* sT = reinterpret_cast<float*>(smem + SM_BUF);  // 128 x 132
        #pragma unroll
        for (int mi = 0; mi < 4; mi++) {
            #pragma unroll
            for (int h = 0; h < 2; h++) {
                const int rl = mloc + mi * 16 + h * 8 + (lane >> 2);
                const float sqi = sSqi[rl];
                #pragma unroll
                for (int ni = 0; ni < 4; ni++) {
                    const int cl = nloc + ni * 8 + (lane & 3) * 2;
                    sT[(cl + 0) * TSTRIDE + rl] = fmaf(-2.0f, acc[mi][ni][h * 2 + 0], sqi + sSqj[cl]);
                    sT[(cl + 1) * TSTRIDE + rl] = fmaf(-2.0f, acc[mi][ni][h * 2 + 1], sqi + sSqj[cl + 1]);
                }
            }
        }
        __syncthreads();
        const int cc = tid >> 1, hf = tid & 1;
        float* dout = g_dist + (size_t)(bj + cc) * NN + bi + hf * 64;
        const float* srow = sT + cc * TSTRIDE + hf * 64;
        #pragma unroll
        for (int i = 0; i < 16; i++)
            reinterpret_cast<float4*>(dout)[i] = reinterpret_cast<const float4*>(srow)[i];
    }
}

// ---------------------------------------------------------------------------
// 3) triplet_kernel: one CTA per row, no atomics, fused last-block finalize
// ---------------------------------------------------------------------------
__global__ __launch_bounds__(256) void triplet_kernel(float* __restrict__ out, int out_size) {
    const int row = blockIdx.x;
    const int cls = row >> 3;
    const int tid = threadIdx.x;
    const float L2E = 1.4426950408889634f;
    const float LN2 = 0.6931471805599453f;

    __shared__ float sP[8], sT[8];
    if (tid < 8) { sP[tid] = g_pos[row * 8 + tid]; sT[tid] = g_thr[row * 8 + tid]; }
    __syncthreads();
    const float4 p0 = *reinterpret_cast<const float4*>(sP);
    const float4 p1 = *reinterpret_cast<const float4*>(sP + 4);
    const float4 t0 = *reinterpret_cast<const float4*>(sT);
    const float4 t1 = *reinterpret_cast<const float4*>(sT + 4);

    const float* drow = g_dist + (size_t)row * NN;
    int ic = 0;
    float tr = 0.0f, ng = 0.0f;

    const float4 dva = *reinterpret_cast<const float4*>(drow + tid * 4);
    const float4 dvb = *reinterpret_cast<const float4*>(drow + 1024 + tid * 4);
    #pragma unroll
    for (int half = 0; half < 2; half++) {
        const int j0 = half * 1024 + tid * 4;
        const float4 dv = half ? dvb : dva;
        const float dd[4] = { dv.x, dv.y, dv.z, dv.w };
        #pragma unroll
        for (int q = 0; q < 4; q++) {
            const int j = j0 + q;
            if ((j >> 3) == cls) continue;
            const float d = dd[q];
            ng += d;
            const float en = fast_exp2(-d * L2E);
            const bool v0 = d < t0.x, v1 = d < t0.y, v2 = d < t0.z, v3 = d < t0.w;
            const bool v4 = d < t1.x, v5 = d < t1.y, v6 = d < t1.z, v7 = d < t1.w;
            ic += (int)v0 + (int)v1 + (int)v2 + (int)v3
                + (int)v4 + (int)v5 + (int)v6 + (int)v7;
            float a0 = (v0 ? fmaf(p0.x, en, 1.0f) : 1.0f) * (v1 ? fmaf(p0.y, en, 1.0f) : 1.0f);
            float a1 = (v2 ? fmaf(p0.z, en, 1.0f) : 1.0f) * (v3 ? fmaf(p0.w, en, 1.0f) : 1.0f);
            float b0 = (v4 ? fmaf(p1.x, en, 1.0f) : 1.0f) * (v5 ? fmaf(p1.y, en, 1.0f) : 1.0f);
            float b1 = (v6 ? fmaf(p1.z, en, 1.0f) : 1.0f) * (v7 ? fmaf(p1.w, en, 1.0f) : 1.0f);
            tr += fast_log2(a0 * a1) + fast_log2(b0 * b1);
        }
    }

    float cnt = (float)ic;
    float trip = LN2 * tr;
    cnt  = warp_sum(cnt);
    trip = warp_sum(trip);
    ng   = warp_sum(ng);
    __shared__ float r0[8], r1[8], r2[8];
    const int w = tid >> 5;
    if ((tid & 31) == 0) { r0[w] = cnt; r1[w] = trip; r2[w] = ng; }
    __syncthreads();
    if (tid == 0) {
        float cs = 0, ts = 0, ns = 0;
        #pragma unroll
        for (int ww = 0; ww < 8; ww++) { cs += r0[ww]; ts += r1[ww]; ns += r2[ww]; }
        g_row[row * 4 + 0] = cs;
        g_row[row * 4 + 1] = ts;
        g_row[row * 4 + 3] = ns;
    }

    // ---- last-block finalize ----
    __syncthreads();
    __shared__ int slast;
    if (tid == 0) {
        __threadfence();
        int o = atomicAdd(&g_done, 1);
        slast = (o == NN - 1);
    }
    __syncthreads();
    if (!slast) return;
    __threadfence();

    double sm = 0, tc = 0, acd = 0, psd = 0, nsd = 0;
    for (int i = tid; i < NN; i += 256) {
        float4 rr = *reinterpret_cast<const float4*>(g_row + i * 4);
        tc += (double)rr.x; psd += (double)rr.z; nsd += (double)rr.w;
        if (rr.x > 0.0f) sm += (double)(rr.y / rr.x);
        else             acd += 1.0;
    }
    #pragma unroll
    for (int o = 16; o; o >>= 1) {
        sm  += __shfl_xor_sync(0xffffffffu, sm, o);
        tc  += __shfl_xor_sync(0xffffffffu, tc, o);
        acd += __shfl_xor_sync(0xffffffffu, acd, o);
        psd += __shfl_xor_sync(0xffffffffu, psd, o);
        nsd += __shfl_xor_sync(0xffffffffu, nsd, o);
    }
    __shared__ double sh[5][8];
    if ((tid & 31) == 0) { sh[0][w] = sm; sh[1][w] = tc; sh[2][w] = acd; sh[3][w] = psd; sh[4][w] = nsd; }
    __syncthreads();
    if (tid == 0) {
        double Sm = 0, Tc = 0, Ac = 0, Ps = 0, Ns = 0;
        #pragma unroll
        for (int ww = 0; ww < 8; ww++) {
            Sm += sh[0][ww]; Tc += sh[1][ww]; Ac += sh[2][ww]; Ps += sh[3][ww]; Ns += sh[4][ww];
        }
        float loss = (Tc > 0.0) ? (float)(Sm / Tc) : 0.0f;
        if (out_size >= 1) out[0] = loss;
        if (out_size >= 2) out[1] = (float)(Ac / (double)NN);
        if (out_size >= 3) out[2] = (float)(Ps / ((double)NN * (KPC - 1)));
        if (out_size >= 4) out[3] = (float)(Ns / ((double)NN * (NN - KPC)));
    }
    for (int idx = 4 + tid; idx < out_size; idx += 256) out[idx] = 0.0f;
}

// ---------------------------------------------------------------------------
extern "C" void kernel_launch(void* const* d_in, const int* in_sizes, int n_in,
                              void* d_out, int out_size) {
    const float* inputs = (const float*)d_in[0];
    (void)in_sizes; (void)n_in;
    float* out = (float*)d_out;

    cudaFuncSetAttribute(gemm_kernel, cudaFuncAttributeMaxDynamicSharedMemorySize, SMEM_TOTAL);
    cudaFuncSetAttribute(gemm_kernel, cudaFuncAttributePreferredSharedMemoryCarveout, 100);

    prep_kernel<<<NN / KPC, 256>>>(inputs);
    gemm_kernel<<<NGEMM, 256, SMEM_TOTAL>>>();
    triplet_kernel<<<NN, 256>>>(out, out_size);
}

// round 13
// speedup vs baseline: 1.6360x; 1.2150x over previous
#include <cuda_runtime.h>
#include <cuda_fp16.h>
#include <cstdint>

#define NN 2048
#define DD 512
#define KPC 8
#define TM 128
#define TN 128
#define KS 64
#define NSLAB (DD / KS)
#define NGEMM 136          // 16*17/2 upper-triangular tiles

// ---------------- scratch (no allocations allowed) ----------------
__device__ __half g_xf[NN * DD];             // fp16 normalized (MMA operand)
__device__ float g_sq[NN];
__device__ float g_dist[(size_t)NN * NN];    // 16 MB distance matrix
__device__ float g_row[NN * 4];              // cnt, trip_sum, pos_sum, neg_sum
__device__ int g_done;

// ---------------- helpers ----------------
__device__ __forceinline__ uint32_t smem_to_u32(const void* p) {
    uint32_t a;
    asm("{ .reg .u64 t; cvta.to.shared.u64 t, %1; cvt.u32.u64 %0, t; }" : "=r"(a) : "l"(p));
    return a;
}
__device__ __forceinline__ float fast_exp2(float x) { float y; asm("ex2.approx.f32 %0, %1;" : "=f"(y) : "f"(x)); return y; }
__device__ __forceinline__ float fast_log2(float x) { float y; asm("lg2.approx.f32 %0, %1;" : "=f"(y) : "f"(x)); return y; }
__device__ __forceinline__ float warp_sum(float v) {
    #pragma unroll
    for (int o = 16; o; o >>= 1) v += __shfl_xor_sync(0xffffffffu, v, o);
    return v;
}

#define CPA(dst, src) \
    asm volatile("cp.async.cg.shared.global [%0], [%1], 16;" :: "r"(dst), "l"(src))
#define CPA_COMMIT() asm volatile("cp.async.commit_group;" ::: "memory")

__device__ __forceinline__ void ldm_x4(uint32_t* r, uint32_t addr) {
    asm volatile("ldmatrix.sync.aligned.m8n8.x4.shared.b16 {%0,%1,%2,%3}, [%4];"
                 : "=r"(r[0]), "=r"(r[1]), "=r"(r[2]), "=r"(r[3]) : "r"(addr));
}
__device__ __forceinline__ void mma_fp16(float* c, const uint32_t* a, uint32_t b0, uint32_t b1) {
    asm volatile(
        "mma.sync.aligned.m16n8k16.row.col.f32.f16.f16.f32 "
        "{%0,%1,%2,%3}, {%4,%5,%6,%7}, {%8,%9}, {%0,%1,%2,%3};"
        : "+f"(c[0]), "+f"(c[1]), "+f"(c[2]), "+f"(c[3])
        : "r"(a[0]), "r"(a[1]), "r"(a[2]), "r"(a[3]), "r"(b0), "r"(b1));
}

// ---------------------------------------------------------------------------
// 1) prep: normalize + fp16 + sq only (positives come from g_dist later)
//    one warp per row, 8 rows per block
// ---------------------------------------------------------------------------
__global__ __launch_bounds__(256) void prep_kernel(const float* __restrict__ in) {
    const int tid = threadIdx.x;
    const int w = tid >> 5;
    const int l = tid & 31;
    const int row = blockIdx.x * 8 + w;
    if (blockIdx.x == 0 && tid == 0) g_done = 0;

    float4 v[4];
    const float4* src = reinterpret_cast<const float4*>(in + row * DD) + l * 4;
    #pragma unroll
    for (int q = 0; q < 4; q++) v[q] = src[q];
    float ss = 0.0f;
    #pragma unroll
    for (int q = 0; q < 4; q++)
        ss += v[q].x * v[q].x + v[q].y * v[q].y + v[q].z * v[q].z + v[q].w * v[q].w;
    ss = warp_sum(ss);
    float s = 4.0f * rsqrtf(ss);

    __half2* pf = reinterpret_cast<__half2*>(g_xf + row * DD + l * 16);
    #pragma unroll
    for (int q = 0; q < 4; q++) {
        pf[q * 2 + 0] = __half2(__float2half_rn(v[q].x * s), __float2half_rn(v[q].y * s));
        pf[q * 2 + 1] = __half2(__float2half_rn(v[q].z * s), __float2half_rn(v[q].w * s));
    }
    if (l == 0) g_sq[row] = ss * s * s;
}

// ---------------------------------------------------------------------------
// 2) gemm_kernel: symmetric HMMA Gram, 136 upper-tri 128x128 tiles.
//    Off-diagonal tiles also store the transposed copy (smem-staged).
// ---------------------------------------------------------------------------
#define SM_SQI 0
#define SM_SQJ 512
#define SM_BUF 1024
#define A_OFF 0
#define B_OFF 16384
#define BUFSZ 32768
#define TSTRIDE 132
#define SMEM_TOTAL (SM_BUF + TM * TSTRIDE * 4)   // 68608 > mainloop's 66560

__device__ __forceinline__ void load_slab_async(uint32_t smb, int buf, int s,
                                                int bi, int bj, int tid) {
    const int k0 = s * KS;
    const uint32_t bufb = smb + SM_BUF + buf * BUFSZ;
    const int row = tid >> 1;
    const int cb = (tid & 1) * 4;
    {
        const char* sp = reinterpret_cast<const char*>(g_xf + (bi + row) * DD + k0);
        uint32_t dA = bufb + A_OFF + row * 128;
        #pragma unroll
        for (int c = 0; c < 4; c++) {
            int ch = cb + c;
            CPA(dA + (((ch ^ (row & 7))) << 4), sp + ch * 16);
        }
    }
    {
        const char* sp = reinterpret_cast<const char*>(g_xf + (bj + row) * DD + k0);
        uint32_t dB = bufb + B_OFF + row * 128;
        #pragma unroll
        for (int c = 0; c < 4; c++) {
            int ch = cb + c;
            CPA(dB + (((ch ^ (row & 7))) << 4), sp + ch * 16);
        }
    }
}

__global__ __launch_bounds__(256, 2) void gemm_kernel() {
    extern __shared__ char smem[];
    const int tid = threadIdx.x;
    const int wid = tid >> 5;
    const int lane = tid & 31;

    // decode upper-triangular tile (ti <= tj)
    int ti = 0, r = blockIdx.x, c = 16;
    while (r >= c) { r -= c; c--; ti++; }
    const int tj = ti + r;
    const int bi = ti * TM;
    const int bj = tj * TN;

    const int mloc = (wid >> 2) * 64;
    const int nloc = (wid & 3) * 32;
    const uint32_t smb = smem_to_u32(smem);
    float* sSqi = reinterpret_cast<float*>(smem + SM_SQI);
    float* sSqj = reinterpret_cast<float*>(smem + SM_SQJ);

    load_slab_async(smb, 0, 0, bi, bj, tid);
    CPA_COMMIT();

    if (tid < 128) sSqi[tid] = g_sq[bi + tid];
    else           sSqj[tid - 128] = g_sq[bj + (tid - 128)];

    float acc[4][4][4];
    #pragma unroll
    for (int mi = 0; mi < 4; mi++)
        #pragma unroll
        for (int ni = 0; ni < 4; ni++)
            #pragma unroll
            for (int rr = 0; rr < 4; rr++) acc[mi][ni][rr] = 0.0f;

    const int rA = (lane & 7) + (((lane >> 3) & 1) << 3);
    const int cSel = lane >> 4;
    const int x7 = lane & 7;
    uint32_t koff[4];
    #pragma unroll
    for (int ks = 0; ks < 4; ks++) koff[ks] = ((uint32_t)((2 * ks + cSel) ^ x7)) << 4;
    const uint32_t arow = (uint32_t)(mloc + rA) * 128;
    const uint32_t brow = (uint32_t)(nloc + rA) * 128;

    #pragma unroll 1
    for (int s = 0; s < NSLAB; s++) {
        const int b = s & 1;
        if (s + 1 < NSLAB) { load_slab_async(smb, 1 - b, s + 1, bi, bj, tid); CPA_COMMIT(); }
        if (s + 1 < NSLAB) asm volatile("cp.async.wait_group 1;" ::: "memory");
        else               asm volatile("cp.async.wait_group 0;" ::: "memory");
        __syncthreads();

        const uint32_t base = smb + SM_BUF + b * BUFSZ;
        const uint32_t baseA = base + A_OFF + arow;
        const uint32_t baseB = base + B_OFF + brow;
        #pragma unroll
        for (int ks = 0; ks < 4; ks++) {
            uint32_t af[4][4];
            #pragma unroll
            for (int mi = 0; mi < 4; mi++) ldm_x4(af[mi], baseA + mi * (16 * 128) + koff[ks]);
            uint32_t bfr[2][4];
            #pragma unroll
            for (int nt = 0; nt < 2; nt++) ldm_x4(bfr[nt], baseB + nt * (16 * 128) + koff[ks]);
            #pragma unroll
            for (int mi = 0; mi < 4; mi++)
                #pragma unroll
                for (int nt = 0; nt < 2; nt++) {
                    mma_fp16(acc[mi][2 * nt],     af[mi], bfr[nt][0], bfr[nt][2]);
                    mma_fp16(acc[mi][2 * nt + 1], af[mi], bfr[nt][1], bfr[nt][3]);
                }
        }
        __syncthreads();
    }

    // normal-orientation store: d = sqi + sqj - 2*dot
    #pragma unroll
    for (int mi = 0; mi < 4; mi++) {
        #pragma unroll
        for (int h = 0; h < 2; h++) {
            const int rl = mloc + mi * 16 + h * 8 + (lane >> 2);
            const float sqi = sSqi[rl];
            float* drow = g_dist + (size_t)(bi + rl) * NN + bj;
            #pragma unroll
            for (int ni = 0; ni < 4; ni++) {
                const int cl = nloc + ni * 8 + (lane & 3) * 2;
                float2 o;
                o.x = fmaf(-2.0f, acc[mi][ni][h * 2 + 0], sqi + sSqj[cl]);
                o.y = fmaf(-2.0f, acc[mi][ni][h * 2 + 1], sqi + sSqj[cl + 1]);
                *reinterpret_cast<float2*>(drow + cl) = o;
            }
        }
    }

    // transposed copy for off-diagonal tiles, staged through smem for coalescing
    if (ti != tj) {
        float* sT = reinterpret_cast<float*>(smem + SM_BUF);  // 128 x 132
        #pragma unroll
        for (int mi = 0; mi < 4; mi++) {
            #pragma unroll
            for (int h = 0; h < 2; h++) {
                const int rl = mloc + mi * 16 + h * 8 + (lane >> 2);
                const float sqi = sSqi[rl];
                #pragma unroll
                for (int ni = 0; ni < 4; ni++) {
                    const int cl = nloc + ni * 8 + (lane & 3) * 2;
                    sT[(cl + 0) * TSTRIDE + rl] = fmaf(-2.0f, acc[mi][ni][h * 2 + 0], sqi + sSqj[cl]);
                    sT[(cl + 1) * TSTRIDE + rl] = fmaf(-2.0f, acc[mi][ni][h * 2 + 1], sqi + sSqj[cl + 1]);
                }
            }
        }
        __syncthreads();
        const int cc = tid >> 1, hf = tid & 1;
        float* dout = g_dist + (size_t)(bj + cc) * NN + bi + hf * 64;
        const float* srow = sT + cc * TSTRIDE + hf * 64;
        #pragma unroll
        for (int i = 0; i < 16; i++)
            reinterpret_cast<float4*>(dout)[i] = reinterpret_cast<const float4*>(srow)[i];
    }
}

// ---------------------------------------------------------------------------
// 3) triplet_kernel: one CTA per row; positives read from g_dist;
//    no atomics; fused last-block finalize
// ---------------------------------------------------------------------------
__global__ __launch_bounds__(256) void triplet_kernel(float* __restrict__ out, int out_size) {
    const int row = blockIdx.x;
    const int cls = row >> 3;
    const int tid = threadIdx.x;
    const float L2E = 1.4426950408889634f;
    const float LN2 = 0.6931471805599453f;

    const float* drow = g_dist + (size_t)row * NN;

    // positives preamble: 8 intra-class dists from this row
    __shared__ float sP[8], sT[8];
    if (tid < 8) {
        const int j = cls * KPC + tid;
        const float p = drow[j];
        const bool self = (j == row);
        sP[tid] = self ? 0.0f : fast_exp2(p * L2E);
        sT[tid] = self ? -1.0e30f : (p + 2.9447e-4f);
        float ps = self ? 0.0f : p;
        ps += __shfl_xor_sync(0x000000ffu, ps, 1);
        ps += __shfl_xor_sync(0x000000ffu, ps, 2);
        ps += __shfl_xor_sync(0x000000ffu, ps, 4);
        if (tid == 0) g_row[row * 4 + 2] = ps;
    }
    __syncthreads();
    const float4 p0 = *reinterpret_cast<const float4*>(sP);
    const float4 p1 = *reinterpret_cast<const float4*>(sP + 4);
    const float4 t0 = *reinterpret_cast<const float4*>(sT);
    const float4 t1 = *reinterpret_cast<const float4*>(sT + 4);

    int ic = 0;
    float tr = 0.0f, ng = 0.0f;

    const float4 dva = *reinterpret_cast<const float4*>(drow + tid * 4);
    const float4 dvb = *reinterpret_cast<const float4*>(drow + 1024 + tid * 4);
    #pragma unroll
    for (int half = 0; half < 2; half++) {
        const int j0 = half * 1024 + tid * 4;
        const float4 dv = half ? dvb : dva;
        const float dd[4] = { dv.x, dv.y, dv.z, dv.w };
        #pragma unroll
        for (int q = 0; q < 4; q++) {
            const int j = j0 + q;
            if ((j >> 3) == cls) continue;
            const float d = dd[q];
            ng += d;
            const float en = fast_exp2(-d * L2E);
            const bool v0 = d < t0.x, v1 = d < t0.y, v2 = d < t0.z, v3 = d < t0.w;
            const bool v4 = d < t1.x, v5 = d < t1.y, v6 = d < t1.z, v7 = d < t1.w;
            ic += (int)v0 + (int)v1 + (int)v2 + (int)v3
                + (int)v4 + (int)v5 + (int)v6 + (int)v7;
            float a0 = (v0 ? fmaf(p0.x, en, 1.0f) : 1.0f) * (v1 ? fmaf(p0.y, en, 1.0f) : 1.0f);
            float a1 = (v2 ? fmaf(p0.z, en, 1.0f) : 1.0f) * (v3 ? fmaf(p0.w, en, 1.0f) : 1.0f);
            float b0 = (v4 ? fmaf(p1.x, en, 1.0f) : 1.0f) * (v5 ? fmaf(p1.y, en, 1.0f) : 1.0f);
            float b1 = (v6 ? fmaf(p1.z, en, 1.0f) : 1.0f) * (v7 ? fmaf(p1.w, en, 1.0f) : 1.0f);
            tr += fast_log2(a0 * a1) + fast_log2(b0 * b1);
        }
    }

    float cnt = (float)ic;
    float trip = LN2 * tr;
    cnt  = warp_sum(cnt);
    trip = warp_sum(trip);
    ng   = warp_sum(ng);
    __shared__ float r0[8], r1[8], r2[8];
    const int w = tid >> 5;
    if ((tid & 31) == 0) { r0[w] = cnt; r1[w] = trip; r2[w] = ng; }
    __syncthreads();
    if (tid == 0) {
        float cs = 0, ts = 0, ns = 0;
        #pragma unroll
        for (int ww = 0; ww < 8; ww++) { cs += r0[ww]; ts += r1[ww]; ns += r2[ww]; }
        g_row[row * 4 + 0] = cs;
        g_row[row * 4 + 1] = ts;
        g_row[row * 4 + 3] = ns;
    }

    // ---- last-block finalize ----
    __syncthreads();
    __shared__ int slast;
    if (tid == 0) {
        __threadfence();
        int o = atomicAdd(&g_done, 1);
        slast = (o == NN - 1);
    }
    __syncthreads();
    if (!slast) return;
    __threadfence();

    double sm = 0, tc = 0, acd = 0, psd = 0, nsd = 0;
    for (int i = tid; i < NN; i += 256) {
        float4 rr = *reinterpret_cast<const float4*>(g_row + i * 4);
        tc += (double)rr.x; psd += (double)rr.z; nsd += (double)rr.w;
        if (rr.x > 0.0f) sm += (double)(rr.y / rr.x);
        else             acd += 1.0;
    }
    #pragma unroll
    for (int o = 16; o; o >>= 1) {
        sm  += __shfl_xor_sync(0xffffffffu, sm, o);
        tc  += __shfl_xor_sync(0xffffffffu, tc, o);
        acd += __shfl_xor_sync(0xffffffffu, acd, o);
        psd += __shfl_xor_sync(0xffffffffu, psd, o);
        nsd += __shfl_xor_sync(0xffffffffu, nsd, o);
    }
    __shared__ double sh[5][8];
    if ((tid & 31) == 0) { sh[0][w] = sm; sh[1][w] = tc; sh[2][w] = acd; sh[3][w] = psd; sh[4][w] = nsd; }
    __syncthreads();
    if (tid == 0) {
        double Sm = 0, Tc = 0, Ac = 0, Ps = 0, Ns = 0;
        #pragma unroll
        for (int ww = 0; ww < 8; ww++) {
            Sm += sh[0][ww]; Tc += sh[1][ww]; Ac += sh[2][ww]; Ps += sh[3][ww]; Ns += sh[4][ww];
        }
        float loss = (Tc > 0.0) ? (float)(Sm / Tc) : 0.0f;
        if (out_size >= 1) out[0] = loss;
        if (out_size >= 2) out[1] = (float)(Ac / (double)NN);
        if (out_size >= 3) out[2] = (float)(Ps / ((double)NN * (KPC - 1)));
        if (out_size >= 4) out[3] = (float)(Ns / ((double)NN * (NN - KPC)));
    }
    for (int idx = 4 + tid; idx < out_size; idx += 256) out[idx] = 0.0f;
}

// ---------------------------------------------------------------------------
extern "C" void kernel_launch(void* const* d_in, const int* in_sizes, int n_in,
                              void* d_out, int out_size) {
    const float* inputs = (const float*)d_in[0];
    (void)in_sizes; (void)n_in;
    float* out = (float*)d_out;

    cudaFuncSetAttribute(gemm_kernel, cudaFuncAttributeMaxDynamicSharedMemorySize, SMEM_TOTAL);
    cudaFuncSetAttribute(gemm_kernel, cudaFuncAttributePreferredSharedMemoryCarveout, 100);

    prep_kernel<<<NN / 8, 256>>>(inputs);
    gemm_kernel<<<NGEMM, 256, SMEM_TOTAL>>>();
    triplet_kernel<<<NN, 256>>>(out, out_size);
}